// round 6
// baseline (speedup 1.0000x reference)
#include <cuda_runtime.h>
#include <stdint.h>

// Problem shapes (fixed by the dataset):
//   lstm : [B, S, C]  float32  = [4, 256, 128]
//   slic : [B, H, W]  int32    = [4, 512, 512], values in [1, S]
//   out  : [B, H, W, C] float32
//
// Pure gather, store-bandwidth bound (~512 MiB written). One warp per pixel:
// each lane moves one float4 (32 lanes * 16B = 512B = C row), stores fully
// cover 128B sectors -> no RFO traffic. lstm (128KiB/batch) lives in L1.

namespace {
constexpr int B = 4;
constexpr int S = 256;
constexpr int C = 128;          // floats per pixel row
constexpr int HW = 512 * 512;   // = 1 << 18
constexpr int HW_SHIFT = 18;
constexpr long long NPIX = (long long)B * HW;   // 1,048,576
constexpr int WARPS_PER_BLOCK = 8;              // 256 threads
constexpr int THREADS = WARPS_PER_BLOCK * 32;
}

__global__ __launch_bounds__(THREADS)
void convert2image_gather(const float* __restrict__ lstm,
                          const int*   __restrict__ slic,
                          float*       __restrict__ out)
{
    const int lane = threadIdx.x & 31;
    const int warp = threadIdx.x >> 5;
    const long long p = (long long)blockIdx.x * WARPS_PER_BLOCK + warp;
    if (p >= NPIX) return;   // grid sized exactly; kept for safety

    // Warp-uniform segment id (single broadcast LDG).
    const int seg = __ldg(&slic[p]) - 1;           // 0-based row in [0, S)
    const int b   = (int)(p >> HW_SHIFT);

    const float4* __restrict__ src =
        reinterpret_cast<const float4*>(lstm + ((long long)(b * S + seg)) * C);
    float4* __restrict__ dst =
        reinterpret_cast<float4*>(out + p * (long long)C);

    // C = 128 floats = 32 float4 -> exactly one per lane.
    dst[lane] = __ldg(&src[lane]);
}

extern "C" void kernel_launch(void* const* d_in, const int* in_sizes, int n_in,
                              void* d_out, int out_size)
{
    const float* lstm = (const float*)d_in[0];   // [B, S, C] float32
    const int*   slic = (const int*)d_in[1];     // [B, H, W] int32
    float*       out  = (float*)d_out;           // [B, H, W, C] float32

    (void)in_sizes; (void)n_in; (void)out_size;

    const int grid = (int)((NPIX + WARPS_PER_BLOCK - 1) / WARPS_PER_BLOCK); // 131072
    convert2image_gather<<<grid, THREADS>>>(lstm, slic, out);
}

// round 7
// speedup vs baseline: 1.6861x; 1.6861x over previous
#include <cuda_runtime.h>
#include <stdint.h>

// Shapes (fixed):
//   lstm : [4, 256, 128] f32   (512 KiB total -> lives in L1/L2)
//   slic : [4, 512, 512] i32   (4 MiB)
//   out  : [4, 512, 512, 128] f32 (512 MiB written -> the bound)
//
// R6 change: 4 pixels per warp, fully unrolled -> MLP=4 per thread on the
// slic->src->store chain (R5 profile showed all pipes <50% = latency-bound).
// Streaming stores (__stcs) keep the write-once out stream from evicting the
// hot lstm rows from L2.

namespace {
constexpr int S = 256;
constexpr int C = 128;                 // floats per pixel row
constexpr int HW_SHIFT = 18;           // 512*512 = 1<<18
constexpr long long NPIX = 4LL << HW_SHIFT;   // 1,048,576
constexpr int PIX_PER_WARP = 4;
constexpr int WARPS_PER_BLOCK = 8;     // 256 threads
constexpr int THREADS = WARPS_PER_BLOCK * 32;
constexpr int PIX_PER_BLOCK = WARPS_PER_BLOCK * PIX_PER_WARP;   // 32
}

__global__ __launch_bounds__(THREADS)
void convert2image_gather4(const float* __restrict__ lstm,
                           const int*   __restrict__ slic,
                           float*       __restrict__ out)
{
    const int lane = threadIdx.x & 31;
    const int warp = threadIdx.x >> 5;

    // First pixel of this warp's group of 4 (consecutive).
    const long long p0 = ((long long)blockIdx.x * WARPS_PER_BLOCK + warp)
                         * PIX_PER_WARP;

    // All 4 pixels share a batch: p0 % 4 == 0 and HW is a multiple of 4.
    const int b = (int)(p0 >> HW_SHIFT);
    const float* __restrict__ lstm_b = lstm + (long long)b * S * C;

    // 1) Four independent warp-uniform id loads (issue together).
    int seg[PIX_PER_WARP];
#pragma unroll
    for (int i = 0; i < PIX_PER_WARP; ++i)
        seg[i] = __ldg(&slic[p0 + i]) - 1;

    // 2) Four independent gather loads (L1-resident lstm rows).
    float4 v[PIX_PER_WARP];
#pragma unroll
    for (int i = 0; i < PIX_PER_WARP; ++i) {
        const float4* src =
            reinterpret_cast<const float4*>(lstm_b + (long long)seg[i] * C);
        v[i] = __ldg(&src[lane]);
    }

    // 3) Four independent streaming stores: warp writes 2 KB contiguous.
    float4* __restrict__ dst =
        reinterpret_cast<float4*>(out + p0 * (long long)C);
#pragma unroll
    for (int i = 0; i < PIX_PER_WARP; ++i)
        __stcs(&dst[i * 32 + lane], v[i]);
}

extern "C" void kernel_launch(void* const* d_in, const int* in_sizes, int n_in,
                              void* d_out, int out_size)
{
    const float* lstm = (const float*)d_in[0];
    const int*   slic = (const int*)d_in[1];
    float*       out  = (float*)d_out;

    (void)in_sizes; (void)n_in; (void)out_size;

    const int grid = (int)(NPIX / PIX_PER_BLOCK);   // 32768, exact
    convert2image_gather4<<<grid, THREADS>>>(lstm, slic, out);
}